// round 15
// baseline (speedup 1.0000x reference)
#include <cuda_runtime.h>
#include <cstdint>

// ROI-align pooling R14: dual-bin + FORCED front-batched loads.
// img (1,128,128,1024) NHWC fp32, rois (1,256,4), out (1,256,7,7,1024) fp32.
//
// R10 showed regs=32 -> ptxas serialized the "8 independent" loads to ~3-4
// in flight. Here the 8 corner loads are volatile inline-PTX ld.global.nc.v4
// issued consecutively: un-sinkable, all destinations live -> true MLP=8.
// __launch_bounds__(256,4) grants the ~60-reg budget (occ ~50%, still far
// above the Little's-law requirement for full bandwidth).

#define POOL  7
#define NROIS 256
#define HH    128
#define WW    128
#define CC    1024
#define NBINS (NROIS * POOL * POOL)   // 12544
#define HALF  (NBINS / 2)             // 6272

__device__ int4   g_offs[NBINS];
__device__ float2 g_ts[NBINS];

__global__ void setup_kernel(const float* __restrict__ rois)
{
    const int bin = blockIdx.x * blockDim.x + threadIdx.x;
    if (bin >= NBINS) return;

    const int roi = bin / (POOL * POOL);
    const int b49 = bin - roi * (POOL * POOL);
    const int iy  = b49 / POOL;
    const int ix  = b49 - iy * POOL;

    const float4 r = reinterpret_cast<const float4*>(rois)[roi];
    const int x0 = (int)(r.x * 0.0625f);
    const int y0 = (int)(r.y * 0.0625f);
    const int w  = (int)(r.z * 0.0625f);
    const int h  = (int)(r.w * 0.0625f);

    // identical fp32 math to reference
    const float sy = (float)iy * ((float)h / (float)POOL);
    const float sx = (float)ix * ((float)w / (float)POOL);
    const float fy = floorf(sy);
    const float fx = floorf(sx);
    const float ty = sy - fy;
    const float tx = sx - fx;

    const int y_lo = (int)fy;
    const int x_lo = (int)fx;
    const int y_hi = min(y_lo + 1, max(h - 1, 0));
    const int x_hi = min(x_lo + 1, max(w - 1, 0));

    const int gy0 = min(max(y0 + y_lo, 0), HH - 1);
    const int gy1 = min(max(y0 + y_hi, 0), HH - 1);
    const int gx0 = min(max(x0 + x_lo, 0), WW - 1);
    const int gx1 = min(max(x0 + x_hi, 0), WW - 1);

    // Fold dead-weight / clamp-identical hi corners onto lo corner (bit-exact).
    const int ex = (tx != 0.0f && gx1 != gx0) ? gx1 : gx0;
    const int ey = (ty != 0.0f && gy1 != gy0) ? gy1 : gy0;

    const int c4 = CC / 4;
    int4 o;
    o.x = (gy0 * WW + gx0) * c4;
    o.y = (gy0 * WW + ex ) * c4;
    o.z = (ey  * WW + gx0) * c4;
    o.w = (ey  * WW + ex ) * c4;
    g_offs[bin] = o;
    g_ts[bin]   = make_float2(tx, ty);
}

// Volatile so consecutive loads cannot be reordered/sunk by the compiler:
// all issued back-to-back, all destinations live -> genuine MLP.
__device__ __forceinline__ float4 ldg128(const float4* p)
{
    float4 v;
    asm volatile("ld.global.nc.v4.f32 {%0,%1,%2,%3}, [%4];"
                 : "=f"(v.x), "=f"(v.y), "=f"(v.z), "=f"(v.w)
                 : "l"(p));
    return v;
}

__device__ __forceinline__ float4 lerp2(float4 a, float4 b, float4 c, float4 d,
                                        float tx, float ty)
{
    float4 r;
    float top, bot;
    top = a.x + tx * (b.x - a.x);
    bot = c.x + tx * (d.x - c.x);
    r.x = top + ty * (bot - top);
    top = a.y + tx * (b.y - a.y);
    bot = c.y + tx * (d.y - c.y);
    r.y = top + ty * (bot - top);
    top = a.z + tx * (b.z - a.z);
    bot = c.z + tx * (d.z - c.z);
    r.z = top + ty * (bot - top);
    top = a.w + tx * (b.w - a.w);
    bot = c.w + tx * (d.w - c.w);
    r.w = top + ty * (bot - top);
    return r;
}

__global__ __launch_bounds__(256, 4)
void roi_pool_kernel(const float* __restrict__ img,
                     float* __restrict__ out)
{
    const int t    = threadIdx.x;       // 0..255: one float4 lane
    const int bin0 = blockIdx.x;        // 0..6271
    const int bin1 = bin0 + HALF;       // 6272..12543

    const float4* __restrict__ imgv = reinterpret_cast<const float4*>(img);
    float4* __restrict__ outv = reinterpret_cast<float4*>(out);

    // Independent param fetches (batch together).
    const int4   o0  = g_offs[bin0];
    const int4   o1  = g_offs[bin1];
    const float2 tw0 = g_ts[bin0];
    const float2 tw1 = g_ts[bin1];

    // 8 forced-batched corner loads: true MLP = 8.
    const float4 a0 = ldg128(imgv + o0.x + t);
    const float4 b0 = ldg128(imgv + o0.y + t);
    const float4 c0 = ldg128(imgv + o0.z + t);
    const float4 d0 = ldg128(imgv + o0.w + t);
    const float4 a1 = ldg128(imgv + o1.x + t);
    const float4 b1 = ldg128(imgv + o1.y + t);
    const float4 c1 = ldg128(imgv + o1.z + t);
    const float4 d1 = ldg128(imgv + o1.w + t);

    const float4 r0 = lerp2(a0, b0, c0, d0, tw0.x, tw0.y);
    outv[(size_t)bin0 * (CC / 4) + t] = r0;

    const float4 r1 = lerp2(a1, b1, c1, d1, tw1.x, tw1.y);
    outv[(size_t)bin1 * (CC / 4) + t] = r1;
}

extern "C" void kernel_launch(void* const* d_in, const int* in_sizes, int n_in,
                              void* d_out, int out_size)
{
    const float* img  = (const float*)d_in[0];
    const float* rois = (const float*)d_in[1];
    if (n_in >= 2 && in_sizes[0] < in_sizes[1]) {
        img  = (const float*)d_in[1];
        rois = (const float*)d_in[0];
    }
    float* out = (float*)d_out;

    setup_kernel<<<(NBINS + 255) / 256, 256>>>(rois);
    roi_pool_kernel<<<HALF, 256>>>(img, out);
}